// round 1
// baseline (speedup 1.0000x reference)
#include <cuda_runtime.h>
#include <cstdint>

#define C_DIM 256
#define DF_DIM 1024
#define NB 8
#define H0 128
#define W0 128
#define T0 (NB*H0*W0)      /* 131072 */
#define H1 32
#define W1 32
#define T1 (NB*H1*W1)      /* 8192 */
#define NHEADS 8
#define DH 32
#define WS 8
#define LWIN 64

// ------------------------------------------------------------------
// Scratch (device globals — allocation-free)
// ------------------------------------------------------------------
__device__ float g_bufA [(size_t)T0*C_DIM];
__device__ float g_bufB [(size_t)T0*C_DIM];
__device__ float g_bufQ [(size_t)T0*C_DIM];
__device__ float g_bufK [(size_t)T0*C_DIM];
__device__ float g_bufV [(size_t)T0*C_DIM];
__device__ float g_bufO [(size_t)T0*C_DIM];
__device__ float g_bufL0[(size_t)T0*C_DIM];
__device__ float g_bufF [(size_t)T0*DF_DIM];
__device__ float g_bufKV[(size_t)T1*C_DIM];

// ------------------------------------------------------------------
// Tiled transpose: per-batch [P][Q] -> [Q][P]
// ------------------------------------------------------------------
__global__ void transpose32_kernel(const float* __restrict__ in,
                                   float* __restrict__ out, int P, int Q)
{
    __shared__ float tile[32][33];
    const size_t bofs = (size_t)blockIdx.z * P * Q;
    in  += bofs;
    out += bofs;
    int p0 = blockIdx.y * 32;
    int q0 = blockIdx.x * 32;
    int tx = threadIdx.x, ty = threadIdx.y;
    #pragma unroll
    for (int i = ty; i < 32; i += 8)
        tile[i][tx] = in[(size_t)(p0 + i) * Q + q0 + tx];
    __syncthreads();
    #pragma unroll
    for (int i = ty; i < 32; i += 8)
        out[(size_t)(q0 + i) * P + p0 + tx] = tile[tx][i];
}

// ------------------------------------------------------------------
// SGEMM: C[M,N] = A[M,K] @ B[K,N]  (+bias over N) (+residual) (relu)
// BM=BN=128, BK=8, 256 threads, 8x8 microtile. All dims divide tiles.
// ------------------------------------------------------------------
#define BM 128
#define BN 128
#define BK 8

__global__ __launch_bounds__(256)
void sgemm_kernel(int M, int N, int K,
                  const float* __restrict__ A, const float* __restrict__ B,
                  const float* __restrict__ bias, const float* __restrict__ Rm,
                  float* __restrict__ Cm, int relu)
{
    __shared__ float As[BK][BM];
    __shared__ float Bs[BK][BN];

    const int tid = threadIdx.x;
    const int bx = blockIdx.x;   // over N
    const int by = blockIdx.y;   // over M

    const int aRow = tid >> 1;          // 0..127
    const int aCol = (tid & 1) * 4;     // 0 or 4
    const int bRow = tid >> 5;          // 0..7
    const int bCol = (tid & 31) * 4;    // 0..124

    const int trow = (tid >> 4) * 8;
    const int tcol = (tid & 15) * 8;

    const float* Aptr = A + (size_t)by * BM * K;
    const float* Bptr = B + (size_t)bx * BN;

    float acc[8][8];
    #pragma unroll
    for (int i = 0; i < 8; i++)
        #pragma unroll
        for (int j = 0; j < 8; j++) acc[i][j] = 0.f;

    for (int k0 = 0; k0 < K; k0 += BK) {
        float4 a4 = *(const float4*)(Aptr + (size_t)aRow * K + k0 + aCol);
        As[aCol + 0][aRow] = a4.x;
        As[aCol + 1][aRow] = a4.y;
        As[aCol + 2][aRow] = a4.z;
        As[aCol + 3][aRow] = a4.w;
        *(float4*)&Bs[bRow][bCol] =
            *(const float4*)(Bptr + (size_t)(k0 + bRow) * N + bCol);
        __syncthreads();

        #pragma unroll
        for (int k = 0; k < BK; k++) {
            float ar[8], br[8];
            float4 t0 = *(const float4*)&As[k][trow];
            float4 t1 = *(const float4*)&As[k][trow + 4];
            ar[0]=t0.x; ar[1]=t0.y; ar[2]=t0.z; ar[3]=t0.w;
            ar[4]=t1.x; ar[5]=t1.y; ar[6]=t1.z; ar[7]=t1.w;
            float4 u0 = *(const float4*)&Bs[k][tcol];
            float4 u1 = *(const float4*)&Bs[k][tcol + 4];
            br[0]=u0.x; br[1]=u0.y; br[2]=u0.z; br[3]=u0.w;
            br[4]=u1.x; br[5]=u1.y; br[6]=u1.z; br[7]=u1.w;
            #pragma unroll
            for (int i = 0; i < 8; i++)
                #pragma unroll
                for (int j = 0; j < 8; j++)
                    acc[i][j] += ar[i] * br[j];
        }
        __syncthreads();
    }

    const size_t crow0 = (size_t)by * BM + trow;
    const int ccol0 = bx * BN + tcol;
    #pragma unroll
    for (int i = 0; i < 8; i++) {
        size_t base = (crow0 + i) * N + ccol0;
        #pragma unroll
        for (int j = 0; j < 8; j += 4) {
            float4 v = make_float4(acc[i][j], acc[i][j+1], acc[i][j+2], acc[i][j+3]);
            if (bias) {
                float4 bb = *(const float4*)(bias + ccol0 + j);
                v.x += bb.x; v.y += bb.y; v.z += bb.z; v.w += bb.w;
            }
            if (Rm) {
                float4 rr = *(const float4*)(Rm + base + j);
                v.x += rr.x; v.y += rr.y; v.z += rr.z; v.w += rr.w;
            }
            if (relu) {
                v.x = fmaxf(v.x, 0.f); v.y = fmaxf(v.y, 0.f);
                v.z = fmaxf(v.z, 0.f); v.w = fmaxf(v.w, 0.f);
            }
            *(float4*)(Cm + base + j) = v;
        }
    }
}

// ------------------------------------------------------------------
// Windowed attention. One block = (window, head). 64 threads.
// q token (i,j) of window (n,wh,ww)  -> (wh*8+i, ww*8+j) in qH x qW
// k token (i,j)                      -> ((wh*ks+i)%kH, (ww*ks+j)%kW)
//  (self: ks=8, kH=qH, no wrap; cross: ks=2 on 32x32 circular map)
// ------------------------------------------------------------------
__global__ __launch_bounds__(64)
void win_attn_kernel(const float* __restrict__ Qm, const float* __restrict__ Km,
                     const float* __restrict__ Vm, float* __restrict__ Om,
                     int qH, int qW, int kH, int kW, int ks)
{
    __shared__ float Qs[LWIN][36];
    __shared__ float Ks[LWIN][36];
    __shared__ float Vs[LWIN][36];

    const int tid  = threadIdx.x;
    const int head = blockIdx.y;
    const int win  = blockIdx.x;
    const int nWw  = qW / WS;
    const int wpb  = (qH / WS) * nWw;
    const int n    = win / wpb;
    const int r    = win % wpb;
    const int wh   = r / nWw, ww = r % nWw;

    const size_t qbase = (size_t)n * qH * qW;
    const size_t kbase = (size_t)n * kH * kW;
    const int co = head * DH;

    // cooperative load: 512 float4 per matrix, 64 threads x 8 iters
    #pragma unroll
    for (int it = 0; it < 8; it++) {
        int idx = tid + it * 64;
        int row = idx >> 3;
        int c4  = (idx & 7) * 4;
        int i = row >> 3, j = row & 7;
        size_t qt = qbase + (size_t)(wh * WS + i) * qW + (ww * WS + j);
        *(float4*)&Qs[row][c4] = *(const float4*)(Qm + qt * C_DIM + co + c4);
        int ki = (wh * ks + i) % kH;
        int kj = (ww * ks + j) % kW;
        size_t kt = kbase + (size_t)ki * kW + kj;
        *(float4*)&Ks[row][c4] = *(const float4*)(Km + kt * C_DIM + co + c4);
        *(float4*)&Vs[row][c4] = *(const float4*)(Vm + kt * C_DIM + co + c4);
    }
    __syncthreads();

    float q[DH];
    #pragma unroll
    for (int k4 = 0; k4 < 8; k4++) {
        float4 t = *(const float4*)&Qs[tid][k4 * 4];
        q[k4*4] = t.x; q[k4*4+1] = t.y; q[k4*4+2] = t.z; q[k4*4+3] = t.w;
    }

    float s[LWIN];
    float mx = -1e30f;
    #pragma unroll
    for (int j = 0; j < LWIN; j++) {
        float acc = 0.f;
        #pragma unroll
        for (int k4 = 0; k4 < 8; k4++) {
            float4 kv = *(const float4*)&Ks[j][k4 * 4];
            acc += q[k4*4]*kv.x + q[k4*4+1]*kv.y + q[k4*4+2]*kv.z + q[k4*4+3]*kv.w;
        }
        s[j] = acc * 0.17677669529663687f;   // 1/sqrt(32)
        mx = fmaxf(mx, s[j]);
    }
    float denom = 0.f;
    #pragma unroll
    for (int j = 0; j < LWIN; j++) { s[j] = __expf(s[j] - mx); denom += s[j]; }
    const float inv = 1.0f / denom;

    float o[DH];
    #pragma unroll
    for (int d = 0; d < DH; d++) o[d] = 0.f;
    #pragma unroll
    for (int j = 0; j < LWIN; j++) {
        float p = s[j] * inv;
        #pragma unroll
        for (int k4 = 0; k4 < 8; k4++) {
            float4 vv = *(const float4*)&Vs[j][k4 * 4];
            o[k4*4]   += p * vv.x; o[k4*4+1] += p * vv.y;
            o[k4*4+2] += p * vv.z; o[k4*4+3] += p * vv.w;
        }
    }

    int i = tid >> 3, j2 = tid & 7;
    size_t qt = qbase + (size_t)(wh * WS + i) * qW + (ww * WS + j2);
    #pragma unroll
    for (int k4 = 0; k4 < 8; k4++)
        *(float4*)(Om + qt * C_DIM + co + k4 * 4) =
            make_float4(o[k4*4], o[k4*4+1], o[k4*4+2], o[k4*4+3]);
}

// ------------------------------------------------------------------
// LayerNorm over C=256, one warp per token
// ------------------------------------------------------------------
__global__ __launch_bounds__(256)
void ln_kernel(const float* __restrict__ in, float* __restrict__ out,
               const float* __restrict__ g, const float* __restrict__ b, int ntok)
{
    int warp = (blockIdx.x * blockDim.x + threadIdx.x) >> 5;
    if (warp >= ntok) return;
    int lane = threadIdx.x & 31;
    const float* row = in + (size_t)warp * C_DIM;
    float v[8], s = 0.f, s2 = 0.f;
    #pragma unroll
    for (int i = 0; i < 8; i++) {
        v[i] = row[lane + 32 * i];
        s += v[i]; s2 += v[i] * v[i];
    }
    #pragma unroll
    for (int o = 16; o; o >>= 1) {
        s  += __shfl_xor_sync(0xffffffffu, s,  o);
        s2 += __shfl_xor_sync(0xffffffffu, s2, o);
    }
    float mu = s * (1.0f / C_DIM);
    float var = s2 * (1.0f / C_DIM) - mu * mu;
    float rs = rsqrtf(var + 1e-5f);
    float* orow = out + (size_t)warp * C_DIM;
    #pragma unroll
    for (int i = 0; i < 8; i++) {
        int c = lane + 32 * i;
        orow[c] = (v[i] - mu) * rs * g[c] + b[c];
    }
}

// ------------------------------------------------------------------
// 4x4 average pool (NHWC): (8,128,128,256) -> (8,32,32,256)
// ------------------------------------------------------------------
__global__ __launch_bounds__(256)
void avgpool_kernel(const float* __restrict__ in, float* __restrict__ out)
{
    int t = blockIdx.x;            // T1 output tokens
    int c = threadIdx.x;
    int n = t / (H1 * W1);
    int r = t % (H1 * W1);
    int oh = r / W1, ow = r % W1;
    float s = 0.f;
    #pragma unroll
    for (int dy = 0; dy < 4; dy++)
        #pragma unroll
        for (int dx = 0; dx < 4; dx++) {
            size_t tok = (size_t)n * H0 * W0 + (size_t)(oh * 4 + dy) * W0 + (ow * 4 + dx);
            s += in[tok * C_DIM + c];
        }
    out[(size_t)t * C_DIM + c] = s * (1.0f / 16.0f);
}

// ------------------------------------------------------------------
// Host side
// ------------------------------------------------------------------
static inline void gemm(const float* A, const float* B, float* Cc,
                        const float* bias, const float* resid, int relu,
                        int M, int N, int K)
{
    dim3 grid(N / BN, M / BM);
    sgemm_kernel<<<grid, 256>>>(M, N, K, A, B, bias, resid, Cc, relu);
}

extern "C" void kernel_launch(void* const* d_in, const int* in_sizes, int n_in,
                              void* d_out, int out_size)
{
    const float* x       = (const float*)d_in[0];
    const float* sa_wq   = (const float*)d_in[1];
    const float* sa_wk   = (const float*)d_in[2];
    const float* sa_wv   = (const float*)d_in[3];
    const float* sa_wf   = (const float*)d_in[4];
    const float* sa_bf   = (const float*)d_in[5];
    const float* ca_wq   = (const float*)d_in[6];
    const float* ca_wk   = (const float*)d_in[7];
    const float* ca_wv   = (const float*)d_in[8];
    const float* ca_wf   = (const float*)d_in[9];
    const float* ca_bf   = (const float*)d_in[10];
    const float* ln_self_g = (const float*)d_in[11];
    const float* ln_self_b = (const float*)d_in[12];
    const float* ln_cross_g= (const float*)d_in[13];
    const float* ln_cross_b= (const float*)d_in[14];
    const float* ffn_w1  = (const float*)d_in[15];
    const float* ffn_b1  = (const float*)d_in[16];
    const float* ffn_w2  = (const float*)d_in[17];
    const float* ffn_b2  = (const float*)d_in[18];
    const float* ln_out_g= (const float*)d_in[19];
    const float* ln_out_b= (const float*)d_in[20];
    float* out = (float*)d_out;

    float *bufA, *bufB, *bufQ, *bufK, *bufV, *bufO, *bufL0, *bufF, *bufKV;
    cudaGetSymbolAddress((void**)&bufA,  g_bufA);
    cudaGetSymbolAddress((void**)&bufB,  g_bufB);
    cudaGetSymbolAddress((void**)&bufQ,  g_bufQ);
    cudaGetSymbolAddress((void**)&bufK,  g_bufK);
    cudaGetSymbolAddress((void**)&bufV,  g_bufV);
    cudaGetSymbolAddress((void**)&bufO,  g_bufO);
    cudaGetSymbolAddress((void**)&bufL0, g_bufL0);
    cudaGetSymbolAddress((void**)&bufF,  g_bufF);
    cudaGetSymbolAddress((void**)&bufKV, g_bufKV);

    dim3 tb(32, 8);

    // 0. NCHW -> NHWC  (per batch: [256][16384] -> [16384][256])
    transpose32_kernel<<<dim3(H0*W0/32, C_DIM/32, NB), tb>>>(x, bufA, C_DIM, H0*W0);

    // 1. Self-attention level 0 (128x128)
    gemm(bufA, sa_wq, bufQ, nullptr, nullptr, 0, T0, C_DIM, C_DIM);
    gemm(bufA, sa_wk, bufK, nullptr, nullptr, 0, T0, C_DIM, C_DIM);
    gemm(bufA, sa_wv, bufV, nullptr, nullptr, 0, T0, C_DIM, C_DIM);
    win_attn_kernel<<<dim3(NB*16*16, NHEADS), 64>>>(bufQ, bufK, bufV, bufO,
                                                    H0, W0, H0, W0, WS);
    gemm(bufO, sa_wf, bufB, sa_bf, bufA, 0, T0, C_DIM, C_DIM);
    ln_kernel<<<T0/8, 256>>>(bufB, bufL0, ln_self_g, ln_self_b, T0);

    // 2. avgpool 4x4 -> (8,32,32,256) into bufB
    avgpool_kernel<<<T1, 256>>>(bufL0, bufB);

    // 3. Self-attention level 1 (32x32)
    gemm(bufB, sa_wq, bufQ, nullptr, nullptr, 0, T1, C_DIM, C_DIM);
    gemm(bufB, sa_wk, bufK, nullptr, nullptr, 0, T1, C_DIM, C_DIM);
    gemm(bufB, sa_wv, bufV, nullptr, nullptr, 0, T1, C_DIM, C_DIM);
    win_attn_kernel<<<dim3(NB*4*4, NHEADS), 64>>>(bufQ, bufK, bufV, bufO,
                                                  H1, W1, H1, W1, WS);
    gemm(bufO, sa_wf, bufA, sa_bf, bufB, 0, T1, C_DIM, C_DIM);
    ln_kernel<<<T1/8, 256>>>(bufA, bufKV, ln_self_g, ln_self_b, T1);

    // 4. Cross-attention: q = level0 LN output, kv = level1 LN output
    gemm(bufL0, ca_wq, bufQ, nullptr, nullptr, 0, T0, C_DIM, C_DIM);
    gemm(bufKV, ca_wk, bufK, nullptr, nullptr, 0, T1, C_DIM, C_DIM);
    gemm(bufKV, ca_wv, bufV, nullptr, nullptr, 0, T1, C_DIM, C_DIM);
    win_attn_kernel<<<dim3(NB*16*16, NHEADS), 64>>>(bufQ, bufK, bufV, bufO,
                                                    H0, W0, H1, W1, 2);
    gemm(bufO, ca_wf, bufB, ca_bf, bufL0, 0, T0, C_DIM, C_DIM);
    ln_kernel<<<T0/8, 256>>>(bufB, bufA, ln_cross_g, ln_cross_b, T0);

    // 5. FFN + final LN
    gemm(bufA, ffn_w1, bufF, ffn_b1, nullptr, 1, T0, DF_DIM, C_DIM);
    gemm(bufF, ffn_w2, bufB, ffn_b2, bufA, 0, T0, C_DIM, DF_DIM);
    ln_kernel<<<T0/8, 256>>>(bufB, bufQ, ln_out_g, ln_out_b, T0);

    // 6. NHWC -> NCHW
    transpose32_kernel<<<dim3(C_DIM/32, H0*W0/32, NB), tb>>>(bufQ, out, H0*W0, C_DIM);
}

// round 7
// speedup vs baseline: 1.6581x; 1.6581x over previous
#include <cuda_runtime.h>
#include <cuda_bf16.h>
#include <cstdint>

#define C_DIM 256
#define DF_DIM 1024
#define NB 8
#define H0 128
#define W0 128
#define T0 (NB*H0*W0)      /* 131072 */
#define H1 32
#define W1 32
#define T1 (NB*H1*W1)      /* 8192 */
#define NHEADS 8
#define DH 32
#define WS 8
#define LWIN 64

// ==================================================================
// Scratch (device globals — allocation-free)
// ==================================================================
__device__ float g_bufA [(size_t)T0*C_DIM];
__device__ float g_bufB [(size_t)T0*C_DIM];
__device__ float g_bufQ [(size_t)T0*C_DIM];
__device__ float g_bufK [(size_t)T0*C_DIM];
__device__ float g_bufV [(size_t)T0*C_DIM];
__device__ float g_bufO [(size_t)T0*C_DIM];
__device__ float g_bufL0[(size_t)T0*C_DIM];
__device__ float g_bufF [(size_t)T0*DF_DIM];
__device__ float g_bufKV[(size_t)T1*C_DIM];
// bf16 split operands
__device__ __nv_bfloat16 g_ash[(size_t)T0*DF_DIM];
__device__ __nv_bfloat16 g_asl[(size_t)T0*DF_DIM];
__device__ __nv_bfloat16 g_wth[1048576];
__device__ __nv_bfloat16 g_wtl[1048576];

// ==================================================================
// PTX helpers (generic: ldmatrix / mma.sync / cp.async)
// ==================================================================
__device__ __forceinline__ uint32_t smem_u32(const void* p) {
    uint32_t a;
    asm("{ .reg .u64 t; cvta.to.shared.u64 t, %1; cvt.u32.u64 %0, t; }"
        : "=r"(a) : "l"(p));
    return a;
}

#define CP_ASYNC16(dst, src) \
    asm volatile("cp.async.cg.shared.global [%0], [%1], 16;" :: "r"(dst), "l"(src) : "memory")
#define CP_COMMIT() asm volatile("cp.async.commit_group;" ::: "memory")

__device__ __forceinline__ void ldm_x4(uint32_t* r, uint32_t addr) {
    asm volatile("ldmatrix.sync.aligned.m8n8.x4.shared.b16 {%0,%1,%2,%3}, [%4];"
        : "=r"(r[0]), "=r"(r[1]), "=r"(r[2]), "=r"(r[3]) : "r"(addr));
}
__device__ __forceinline__ void ldm_x2(uint32_t* r, uint32_t addr) {
    asm volatile("ldmatrix.sync.aligned.m8n8.x2.shared.b16 {%0,%1}, [%2];"
        : "=r"(r[0]), "=r"(r[1]) : "r"(addr));
}
__device__ __forceinline__ void mma16816(float* c, const uint32_t* a, const uint32_t* b) {
    asm volatile("mma.sync.aligned.m16n8k16.row.col.f32.bf16.bf16.f32 "
        "{%0,%1,%2,%3}, {%4,%5,%6,%7}, {%8,%9}, {%0,%1,%2,%3};"
        : "+f"(c[0]), "+f"(c[1]), "+f"(c[2]), "+f"(c[3])
        : "r"(a[0]), "r"(a[1]), "r"(a[2]), "r"(a[3]), "r"(b[0]), "r"(b[1]));
}

// ==================================================================
// Tiled transpose: per-batch [P][Q] -> [Q][P]
// ==================================================================
__global__ void transpose32_kernel(const float* __restrict__ in,
                                   float* __restrict__ out, int P, int Q)
{
    __shared__ float tile[32][33];
    const size_t bofs = (size_t)blockIdx.z * P * Q;
    in  += bofs;
    out += bofs;
    int p0 = blockIdx.y * 32;
    int q0 = blockIdx.x * 32;
    int tx = threadIdx.x, ty = threadIdx.y;
    #pragma unroll
    for (int i = ty; i < 32; i += 8)
        tile[i][tx] = in[(size_t)(p0 + i) * Q + q0 + tx];
    __syncthreads();
    #pragma unroll
    for (int i = ty; i < 32; i += 8)
        out[(size_t)(q0 + i) * P + p0 + tx] = tile[tx][i];
}

// ==================================================================
// Split fp32 -> bf16 hi + bf16 lo (elementwise, vectorized)
// ==================================================================
__global__ __launch_bounds__(256)
void split_kernel(const float* __restrict__ in, __nv_bfloat16* __restrict__ hi,
                  __nv_bfloat16* __restrict__ lo, size_t n4)
{
    size_t i = (size_t)blockIdx.x * blockDim.x + threadIdx.x;
    if (i >= n4) return;
    float4 v = ((const float4*)in)[i];
    __nv_bfloat16 h0 = __float2bfloat16(v.x);
    __nv_bfloat16 h1 = __float2bfloat16(v.y);
    __nv_bfloat16 h2 = __float2bfloat16(v.z);
    __nv_bfloat16 h3 = __float2bfloat16(v.w);
    __nv_bfloat16 l0 = __float2bfloat16(v.x - __bfloat162float(h0));
    __nv_bfloat16 l1 = __float2bfloat16(v.y - __bfloat162float(h1));
    __nv_bfloat16 l2 = __float2bfloat16(v.z - __bfloat162float(h2));
    __nv_bfloat16 l3 = __float2bfloat16(v.w - __bfloat162float(h3));
    __nv_bfloat162* hp = (__nv_bfloat162*)hi;
    __nv_bfloat162* lp = (__nv_bfloat162*)lo;
    hp[2*i]   = __nv_bfloat162(h0, h1);
    hp[2*i+1] = __nv_bfloat162(h2, h3);
    lp[2*i]   = __nv_bfloat162(l0, l1);
    lp[2*i+1] = __nv_bfloat162(l2, l3);
}

// ==================================================================
// Transpose + split weights: W[K,N] fp32 -> WT_hi/lo [N,K] bf16
// ==================================================================
__global__ void tsplit_kernel(const float* __restrict__ W,
                              __nv_bfloat16* __restrict__ hi,
                              __nv_bfloat16* __restrict__ lo, int K, int N)
{
    __shared__ float tile[32][33];
    int n0 = blockIdx.x * 32;
    int k0 = blockIdx.y * 32;
    int tx = threadIdx.x, ty = threadIdx.y;
    #pragma unroll
    for (int i = ty; i < 32; i += 8)
        tile[i][tx] = W[(size_t)(k0 + i) * N + n0 + tx];
    __syncthreads();
    #pragma unroll
    for (int i = ty; i < 32; i += 8) {
        float v = tile[tx][i];
        __nv_bfloat16 h = __float2bfloat16(v);
        __nv_bfloat16 l = __float2bfloat16(v - __bfloat162float(h));
        size_t o = (size_t)(n0 + i) * K + k0 + tx;
        hi[o] = h;
        lo[o] = l;
    }
}

// ==================================================================
// mma.sync bf16x3 GEMM:  C[M,N] = (Ah+Al)[M,K] @ (Bh+Bl)[N,K]^T
// D += Ah*Bh + Ah*Bl + Al*Bh ; fp32 accumulators.
// CTA 128x128, BK=32, 8 warps (2x4), warp tile 64x32, 4-stage cp.async.
// ==================================================================
#define BM 128
#define BN 128
#define BK 32
#define LDS 40                         /* padded row, elements */
#define MAT_BYTES (128*LDS*2)          /* 10240 */
#define STG_BYTES (4*MAT_BYTES)        /* 40960: Ah, Al, Bh, Bl */
#define STAGES 4
#define GEMM_SMEM (STAGES*STG_BYTES)   /* 163840 */

__device__ __forceinline__ void load_tiles(uint32_t st,
    const __nv_bfloat16* ah, const __nv_bfloat16* al,
    const __nv_bfloat16* bh, const __nv_bfloat16* bl,
    int K, int k0, int tid)
{
    // Each tile row = 32 bf16 = 64B. 128 rows/matrix, 256 threads:
    // 2 threads per row, each thread covers 32B (two 16B cp.async chunks).
    int row = tid >> 1;
    int cb  = (tid & 1) * 32;                 // byte offset within row: 0 or 32
    uint32_t doff = (uint32_t)row * (LDS*2) + cb;
    const char* pa = (const char*)(ah + (size_t)row * K + k0) + cb;
    const char* pl = (const char*)(al + (size_t)row * K + k0) + cb;
    const char* pb = (const char*)(bh + (size_t)row * K + k0) + cb;
    const char* pc = (const char*)(bl + (size_t)row * K + k0) + cb;
    CP_ASYNC16(st + doff,                    pa);
    CP_ASYNC16(st + doff + 16,               pa + 16);
    CP_ASYNC16(st + MAT_BYTES + doff,        pl);
    CP_ASYNC16(st + MAT_BYTES + doff + 16,   pl + 16);
    CP_ASYNC16(st + 2*MAT_BYTES + doff,      pb);
    CP_ASYNC16(st + 2*MAT_BYTES + doff + 16, pb + 16);
    CP_ASYNC16(st + 3*MAT_BYTES + doff,      pc);
    CP_ASYNC16(st + 3*MAT_BYTES + doff + 16, pc + 16);
}

__global__ __launch_bounds__(256)
void gemm_tc_kernel(int M, int N, int K,
    const __nv_bfloat16* __restrict__ Ah, const __nv_bfloat16* __restrict__ Al,
    const __nv_bfloat16* __restrict__ Bh, const __nv_bfloat16* __restrict__ Bl,
    const float* __restrict__ bias, const float* __restrict__ Rm,
    float* __restrict__ Cm, int relu)
{
    extern __shared__ char smem[];
    const uint32_t sbase = smem_u32(smem);
    const int tid  = threadIdx.x;
    const int wid  = tid >> 5;
    const int lane = tid & 31;
    const int wm = wid >> 2;         // 0..1  (64-row slab)
    const int wn = wid & 3;          // 0..3  (32-col slab)

    const int m0 = blockIdx.x * BM;
    const int n0 = blockIdx.y * BN;
    const __nv_bfloat16* ah = Ah + (size_t)m0 * K;
    const __nv_bfloat16* al = Al + (size_t)m0 * K;
    const __nv_bfloat16* bh = Bh + (size_t)n0 * K;
    const __nv_bfloat16* bl = Bl + (size_t)n0 * K;

    const int NC = K / BK;

    float acc[4][4][4];
    #pragma unroll
    for (int mt = 0; mt < 4; mt++)
        #pragma unroll
        for (int nt = 0; nt < 4; nt++)
            #pragma unroll
            for (int j = 0; j < 4; j++) acc[mt][nt][j] = 0.f;

    // prologue: fill STAGES-1 stages
    #pragma unroll
    for (int s = 0; s < STAGES - 1; s++) {
        if (s < NC) load_tiles(sbase + s * STG_BYTES, ah, al, bh, bl, K, s * BK, tid);
        CP_COMMIT();
    }

    // ldmatrix lane addressing
    const int lr16 = lane & 15;
    const int lc16 = lane >> 4;
    const int lr8  = lr16 & 7;
    const int lc8  = lr16 >> 3;

    for (int i = 0; i < NC; i++) {
        asm volatile("cp.async.wait_group %0;" :: "n"(STAGES - 2));
        __syncthreads();

        int is = i + STAGES - 1;
        if (is < NC) load_tiles(sbase + (is % STAGES) * STG_BYTES,
                                ah, al, bh, bl, K, is * BK, tid);
        CP_COMMIT();

        const uint32_t st  = sbase + (i % STAGES) * STG_BYTES;
        const uint32_t sAh = st;
        const uint32_t sAl = st + MAT_BYTES;
        const uint32_t sBh = st + 2*MAT_BYTES;
        const uint32_t sBl = st + 3*MAT_BYTES;

        #pragma unroll
        for (int ks = 0; ks < 2; ks++) {
            uint32_t ahf[4][4], alf[4][4], bhf[4][2], blf[4][2];
            #pragma unroll
            for (int mt = 0; mt < 4; mt++) {
                uint32_t off = ((uint32_t)(wm*64 + mt*16 + lr16) * LDS
                                + ks*16 + lc16*8) * 2;
                ldm_x4(ahf[mt], sAh + off);
                ldm_x4(alf[mt], sAl + off);
            }
            #pragma unroll
            for (int nt = 0; nt < 4; nt++) {
                uint32_t off = ((uint32_t)(wn*32 + nt*8 + lr8) * LDS
                                + ks*16 + lc8*8) * 2;
                ldm_x2(bhf[nt], sBh + off);
                ldm_x2(blf[nt], sBl + off);
            }
            #pragma unroll
            for (int mt = 0; mt < 4; mt++)
                #pragma unroll
                for (int nt = 0; nt < 4; nt++) {
                    mma16816(acc[mt][nt], ahf[mt], bhf[nt]);
                    mma16816(acc[mt][nt], ahf[mt], blf[nt]);
                    mma16816(acc[mt][nt], alf[mt], bhf[nt]);
                }
        }
    }

    // Epilogue: m16n8 accumulator layout -> gmem, fused bias/resid/relu
    const int rit = lane >> 2;          // row in 16-tile (0..7)
    const int cit = (lane & 3) * 2;     // col pair
    #pragma unroll
    for (int mt = 0; mt < 4; mt++) {
        #pragma unroll
        for (int nt = 0; nt < 4; nt++) {
            int gr0 = m0 + wm*64 + mt*16 + rit;
            int gc  = n0 + wn*32 + nt*8 + cit;
            float v0 = acc[mt][nt][0], v1 = acc[mt][nt][1];
            float v2 = acc[mt][nt][2], v3 = acc[mt][nt][3];
            if (bias) {
                float2 bb = *(const float2*)(bias + gc);
                v0 += bb.x; v1 += bb.y; v2 += bb.x; v3 += bb.y;
            }
            size_t o0 = (size_t)gr0 * N + gc;
            size_t o1 = (size_t)(gr0 + 8) * N + gc;
            if (Rm) {
                float2 r0 = *(const float2*)(Rm + o0);
                float2 r1 = *(const float2*)(Rm + o1);
                v0 += r0.x; v1 += r0.y; v2 += r1.x; v3 += r1.y;
            }
            if (relu) {
                v0 = fmaxf(v0, 0.f); v1 = fmaxf(v1, 0.f);
                v2 = fmaxf(v2, 0.f); v3 = fmaxf(v3, 0.f);
            }
            *(float2*)(Cm + o0) = make_float2(v0, v1);
            *(float2*)(Cm + o1) = make_float2(v2, v3);
        }
    }
}

// ==================================================================
// Windowed attention (unchanged)
// ==================================================================
__global__ __launch_bounds__(64)
void win_attn_kernel(const float* __restrict__ Qm, const float* __restrict__ Km,
                     const float* __restrict__ Vm, float* __restrict__ Om,
                     int qH, int qW, int kH, int kW, int ks)
{
    __shared__ float Qs[LWIN][36];
    __shared__ float Ks[LWIN][36];
    __shared__ float Vs[LWIN][36];

    const int tid  = threadIdx.x;
    const int head = blockIdx.y;
    const int win  = blockIdx.x;
    const int nWw  = qW / WS;
    const int wpb  = (qH / WS) * nWw;
    const int n    = win / wpb;
    const int r    = win % wpb;
    const int wh   = r / nWw, ww = r % nWw;

    const size_t qbase = (size_t)n * qH * qW;
    const size_t kbase = (size_t)n * kH * kW;
    const int co = head * DH;

    #pragma unroll
    for (int it = 0; it < 8; it++) {
        int idx = tid + it * 64;
        int row = idx >> 3;
        int c4  = (idx & 7) * 4;
        int i = row >> 3, j = row & 7;
        size_t qt = qbase + (size_t)(wh * WS + i) * qW + (ww * WS + j);
        *(float4*)&Qs[row][c4] = *(const float4*)(Qm + qt * C_DIM + co + c4);
        int ki = (wh * ks + i) % kH;
        int kj = (ww * ks + j) % kW;
        size_t kt = kbase + (size_t)ki * kW + kj;
        *(float4*)&Ks[row][c4] = *(const float4*)(Km + kt * C_DIM + co + c4);
        *(float4*)&Vs[row][c4] = *(const float4*)(Vm + kt * C_DIM + co + c4);
    }
    __syncthreads();

    float q[DH];
    #pragma unroll
    for (int k4 = 0; k4 < 8; k4++) {
        float4 t = *(const float4*)&Qs[tid][k4 * 4];
        q[k4*4] = t.x; q[k4*4+1] = t.y; q[k4*4+2] = t.z; q[k4*4+3] = t.w;
    }

    float s[LWIN];
    float mx = -1e30f;
    #pragma unroll
    for (int j = 0; j < LWIN; j++) {
        float a = 0.f;
        #pragma unroll
        for (int k4 = 0; k4 < 8; k4++) {
            float4 kv = *(const float4*)&Ks[j][k4 * 4];
            a += q[k4*4]*kv.x + q[k4*4+1]*kv.y + q[k4*4+2]*kv.z + q[k4*4+3]*kv.w;
        }
        s[j] = a * 0.17677669529663687f;
        mx = fmaxf(mx, s[j]);
    }
    float denom = 0.f;
    #pragma unroll
    for (int j = 0; j < LWIN; j++) { s[j] = __expf(s[j] - mx); denom += s[j]; }
    const float inv = 1.0f / denom;

    float o[DH];
    #pragma unroll
    for (int d = 0; d < DH; d++) o[d] = 0.f;
    #pragma unroll
    for (int j = 0; j < LWIN; j++) {
        float p = s[j] * inv;
        #pragma unroll
        for (int k4 = 0; k4 < 8; k4++) {
            float4 vv = *(const float4*)&Vs[j][k4 * 4];
            o[k4*4]   += p * vv.x; o[k4*4+1] += p * vv.y;
            o[k4*4+2] += p * vv.z; o[k4*4+3] += p * vv.w;
        }
    }

    int i = tid >> 3, j2 = tid & 7;
    size_t qt = qbase + (size_t)(wh * WS + i) * qW + (ww * WS + j2);
    #pragma unroll
    for (int k4 = 0; k4 < 8; k4++)
        *(float4*)(Om + qt * C_DIM + co + k4 * 4) =
            make_float4(o[k4*4], o[k4*4+1], o[k4*4+2], o[k4*4+3]);
}

// ==================================================================
// LayerNorm over C=256, one warp per token
// ==================================================================
__global__ __launch_bounds__(256)
void ln_kernel(const float* __restrict__ in, float* __restrict__ out,
               const float* __restrict__ g, const float* __restrict__ b, int ntok)
{
    int warp = (blockIdx.x * blockDim.x + threadIdx.x) >> 5;
    if (warp >= ntok) return;
    int lane = threadIdx.x & 31;
    const float* row = in + (size_t)warp * C_DIM;
    float v[8], s = 0.f, s2 = 0.f;
    #pragma unroll
    for (int i = 0; i < 8; i++) {
        v[i] = row[lane + 32 * i];
        s += v[i]; s2 += v[i] * v[i];
    }
    #pragma unroll
    for (int o = 16; o; o >>= 1) {
        s  += __shfl_xor_sync(0xffffffffu, s,  o);
        s2 += __shfl_xor_sync(0xffffffffu, s2, o);
    }
    float mu = s * (1.0f / C_DIM);
    float var = s2 * (1.0f / C_DIM) - mu * mu;
    float rs = rsqrtf(var + 1e-5f);
    float* orow = out + (size_t)warp * C_DIM;
    #pragma unroll
    for (int i = 0; i < 8; i++) {
        int c = lane + 32 * i;
        orow[c] = (v[i] - mu) * rs * g[c] + b[c];
    }
}

// ==================================================================
// 4x4 average pool (NHWC)
// ==================================================================
__global__ __launch_bounds__(256)
void avgpool_kernel(const float* __restrict__ in, float* __restrict__ out)
{
    int t = blockIdx.x;
    int c = threadIdx.x;
    int n = t / (H1 * W1);
    int r = t % (H1 * W1);
    int oh = r / W1, ow = r % W1;
    float s = 0.f;
    #pragma unroll
    for (int dy = 0; dy < 4; dy++)
        #pragma unroll
        for (int dx = 0; dx < 4; dx++) {
            size_t tok = (size_t)n * H0 * W0 + (size_t)(oh * 4 + dy) * W0 + (ow * 4 + dx);
            s += in[tok * C_DIM + c];
        }
    out[(size_t)t * C_DIM + c] = s * (1.0f / 16.0f);
}

// ==================================================================
// Host side
// ==================================================================
#define WT_SAQ 0
#define WT_SAK 65536
#define WT_SAV 131072
#define WT_SAF 196608
#define WT_CAQ 262144
#define WT_CAK 327680
#define WT_CAV 393216
#define WT_CAF 458752
#define WT_W1  524288
#define WT_W2  786432

extern "C" void kernel_launch(void* const* d_in, const int* in_sizes, int n_in,
                              void* d_out, int out_size)
{
    const float* x       = (const float*)d_in[0];
    const float* sa_wq   = (const float*)d_in[1];
    const float* sa_wk   = (const float*)d_in[2];
    const float* sa_wv   = (const float*)d_in[3];
    const float* sa_wf   = (const float*)d_in[4];
    const float* sa_bf   = (const float*)d_in[5];
    const float* ca_wq   = (const float*)d_in[6];
    const float* ca_wk   = (const float*)d_in[7];
    const float* ca_wv   = (const float*)d_in[8];
    const float* ca_wf   = (const float*)d_in[9];
    const float* ca_bf   = (const float*)d_in[10];
    const float* ln_self_g = (const float*)d_in[11];
    const float* ln_self_b = (const float*)d_in[12];
    const float* ln_cross_g= (const float*)d_in[13];
    const float* ln_cross_b= (const float*)d_in[14];
    const float* ffn_w1  = (const float*)d_in[15];
    const float* ffn_b1  = (const float*)d_in[16];
    const float* ffn_w2  = (const float*)d_in[17];
    const float* ffn_b2  = (const float*)d_in[18];
    const float* ln_out_g= (const float*)d_in[19];
    const float* ln_out_b= (const float*)d_in[20];
    float* out = (float*)d_out;

    float *bufA, *bufB, *bufQ, *bufK, *bufV, *bufO, *bufL0, *bufF, *bufKV;
    __nv_bfloat16 *ash, *asl, *wth, *wtl;
    cudaGetSymbolAddress((void**)&bufA,  g_bufA);
    cudaGetSymbolAddress((void**)&bufB,  g_bufB);
    cudaGetSymbolAddress((void**)&bufQ,  g_bufQ);
    cudaGetSymbolAddress((void**)&bufK,  g_bufK);
    cudaGetSymbolAddress((void**)&bufV,  g_bufV);
    cudaGetSymbolAddress((void**)&bufO,  g_bufO);
    cudaGetSymbolAddress((void**)&bufL0, g_bufL0);
    cudaGetSymbolAddress((void**)&bufF,  g_bufF);
    cudaGetSymbolAddress((void**)&bufKV, g_bufKV);
    cudaGetSymbolAddress((void**)&ash,   g_ash);
    cudaGetSymbolAddress((void**)&asl,   g_asl);
    cudaGetSymbolAddress((void**)&wth,   g_wth);
    cudaGetSymbolAddress((void**)&wtl,   g_wtl);

    cudaFuncSetAttribute(gemm_tc_kernel,
                         cudaFuncAttributeMaxDynamicSharedMemorySize, GEMM_SMEM);

    dim3 tb(32, 8);

    auto gemm = [&](const __nv_bfloat16* Bh, const __nv_bfloat16* Bl,
                    const float* bias, const float* resid, float* Cm,
                    int relu, int M, int N, int K) {
        dim3 grid(M / BM, N / BN);
        gemm_tc_kernel<<<grid, 256, GEMM_SMEM>>>(M, N, K, ash, asl, Bh, Bl,
                                                 bias, resid, Cm, relu);
    };
    auto split = [&](const float* src, size_t n) {
        split_kernel<<<(unsigned)(n / 4 / 256), 256>>>(src, ash, asl, n / 4);
    };

    // --- transpose+split all weights ---
    tsplit_kernel<<<dim3(8, 8),  tb>>>(sa_wq,  wth + WT_SAQ, wtl + WT_SAQ, 256, 256);
    tsplit_kernel<<<dim3(8, 8),  tb>>>(sa_wk,  wth + WT_SAK, wtl + WT_SAK, 256, 256);
    tsplit_kernel<<<dim3(8, 8),  tb>>>(sa_wv,  wth + WT_SAV, wtl + WT_SAV, 256, 256);
    tsplit_kernel<<<dim3(8, 8),  tb>>>(sa_wf,  wth + WT_SAF, wtl + WT_SAF, 256, 256);
    tsplit_kernel<<<dim3(8, 8),  tb>>>(ca_wq,  wth + WT_CAQ, wtl + WT_CAQ, 256, 256);
    tsplit_kernel<<<dim3(8, 8),  tb>>>(ca_wk,  wth + WT_CAK, wtl + WT_CAK, 256, 256);
    tsplit_kernel<<<dim3(8, 8),  tb>>>(ca_wv,  wth + WT_CAV, wtl + WT_CAV, 256, 256);
    tsplit_kernel<<<dim3(8, 8),  tb>>>(ca_wf,  wth + WT_CAF, wtl + WT_CAF, 256, 256);
    tsplit_kernel<<<dim3(32, 8), tb>>>(ffn_w1, wth + WT_W1,  wtl + WT_W1,  256, 1024);
    tsplit_kernel<<<dim3(8, 32), tb>>>(ffn_w2, wth + WT_W2,  wtl + WT_W2,  1024, 256);

    // 0. NCHW -> NHWC
    transpose32_kernel<<<dim3(H0*W0/32, C_DIM/32, NB), tb>>>(x, bufA, C_DIM, H0*W0);

    // 1. Self-attention level 0
    split(bufA, (size_t)T0 * C_DIM);
    gemm(wth + WT_SAQ, wtl + WT_SAQ, nullptr, nullptr, bufQ, 0, T0, C_DIM, C_DIM);
    gemm(wth + WT_SAK, wtl + WT_SAK, nullptr, nullptr, bufK, 0, T0, C_DIM, C_DIM);
    gemm(wth + WT_SAV, wtl + WT_SAV, nullptr, nullptr, bufV, 0, T0, C_DIM, C_DIM);
    win_attn_kernel<<<dim3(NB*16*16, NHEADS), 64>>>(bufQ, bufK, bufV, bufO,
                                                    H0, W0, H0, W0, WS);
    split(bufO, (size_t)T0 * C_DIM);
    gemm(wth + WT_SAF, wtl + WT_SAF, sa_bf, bufA, bufB, 0, T0, C_DIM, C_DIM);
    ln_kernel<<<T0/8, 256>>>(bufB, bufL0, ln_self_g, ln_self_b, T0);

    // 2. avgpool
    avgpool_kernel<<<T1, 256>>>(bufL0, bufB);

    // 3. Self-attention level 1
    split(bufB, (size_t)T1 * C_DIM);
    gemm(wth + WT_SAQ, wtl + WT_SAQ, nullptr, nullptr, bufQ, 0, T1, C_DIM, C_DIM);
    gemm(wth + WT_SAK, wtl + WT_SAK, nullptr, nullptr, bufK, 0, T1, C_DIM, C_DIM);
    gemm(wth + WT_SAV, wtl + WT_SAV, nullptr, nullptr, bufV, 0, T1, C_DIM, C_DIM);
    win_attn_kernel<<<dim3(NB*4*4, NHEADS), 64>>>(bufQ, bufK, bufV, bufO,
                                                  H1, W1, H1, W1, WS);
    split(bufO, (size_t)T1 * C_DIM);
    gemm(wth + WT_SAF, wtl + WT_SAF, sa_bf, bufB, bufA, 0, T1, C_DIM, C_DIM);
    ln_kernel<<<T1/8, 256>>>(bufA, bufKV, ln_self_g, ln_self_b, T1);

    // 4. Cross-attention
    split(bufL0, (size_t)T0 * C_DIM);
    gemm(wth + WT_CAQ, wtl + WT_CAQ, nullptr, nullptr, bufQ, 0, T0, C_DIM, C_DIM);
    split(bufKV, (size_t)T1 * C_DIM);
    gemm(wth + WT_CAK, wtl + WT_CAK, nullptr, nullptr, bufK, 0, T1, C_DIM, C_DIM);
    gemm(wth + WT_CAV, wtl + WT_CAV, nullptr, nullptr, bufV, 0, T1, C_DIM, C_DIM);
    win_attn_kernel<<<dim3(NB*16*16, NHEADS), 64>>>(bufQ, bufK, bufV, bufO,
                                                    H0, W0, H1, W1, 2);
    split(bufO, (size_t)T0 * C_DIM);
    gemm(wth + WT_CAF, wtl + WT_CAF, ca_bf, bufL0, bufB, 0, T0, C_DIM, C_DIM);
    ln_kernel<<<T0/8, 256>>>(bufB, bufA, ln_cross_g, ln_cross_b, T0);

    // 5. FFN + final LN
    split(bufA, (size_t)T0 * C_DIM);
    gemm(wth + WT_W1, wtl + WT_W1, ffn_b1, nullptr, bufF, 1, T0, DF_DIM, C_DIM);
    split(bufF, (size_t)T0 * DF_DIM);
    gemm(wth + WT_W2, wtl + WT_W2, ffn_b2, bufA, bufB, 0, T0, C_DIM, DF_DIM);
    ln_kernel<<<T0/8, 256>>>(bufB, bufQ, ln_out_g, ln_out_b, T0);

    // 6. NHWC -> NCHW
    transpose32_kernel<<<dim3(C_DIM/32, H0*W0/32, NB), tb>>>(bufQ, out, H0*W0, C_DIM);
}